// round 11
// baseline (speedup 1.0000x reference)
#include <cuda_runtime.h>
#include <cuda_bf16.h>
#include <cuda_fp16.h>
#include <cstdint>

#define NN 100000
#define NE 1600000
#define NG 64
#define HID 64
#define INDIM 128

// Scratch (__device__ globals per alloc-free rule)
__device__ __half g_buf1h[NN * 64];  // GEMM output (unscaled), fp16 SpMM source
__device__ float4 g_buf2[NN * 16];   // activations / gated output (fp32)
__device__ float  g_norm_out[NN];
__device__ float  g_norm_in[NN];
__device__ int    g_deg_out[NN];
__device__ int    g_deg_in[NN];
__device__ int    g_fill[NN];
__device__ int    g_row_off[NN];
__device__ int    g_csr_src[NE];
__device__ int    g_total;
__device__ int    g_off[NG + 1];

// ---------------------------------------------------------------------------
__device__ __forceinline__ uint32_t smem_u32(const void* p) {
    uint32_t a;
    asm("{ .reg .u64 t; cvta.to.shared.u64 t, %1; cvt.u32.u64 %0, t; }"
        : "=r"(a) : "l"(p));
    return a;
}
__device__ __forceinline__ void ldm_x4(uint32_t* r, uint32_t addr) {
    asm volatile("ldmatrix.sync.aligned.m8n8.x4.shared.b16 {%0,%1,%2,%3}, [%4];"
                 : "=r"(r[0]), "=r"(r[1]), "=r"(r[2]), "=r"(r[3]) : "r"(addr));
}
__device__ __forceinline__ void mma_16816(float* d, const uint32_t* a,
                                          const uint32_t* b) {
    asm volatile("mma.sync.aligned.m16n8k16.row.col.f32.f16.f16.f32 "
                 "{%0,%1,%2,%3}, {%4,%5,%6,%7}, {%8,%9}, {%0,%1,%2,%3};"
                 : "+f"(d[0]), "+f"(d[1]), "+f"(d[2]), "+f"(d[3])
                 : "r"(a[0]), "r"(a[1]), "r"(a[2]), "r"(a[3]),
                   "r"(b[0]), "r"(b[1]));
}

// ---------------------------------------------------------------------------
__global__ void zero_kernel() {
    int i = blockIdx.x * blockDim.x + threadIdx.x;
    if (i < NN) { g_deg_out[i] = 0; g_deg_in[i] = 0; }
    if (i == 0) g_total = 0;
}

// Degrees + (last block) graph segment bounds via binary search on sorted gid.
__global__ void degree_kernel(const int* __restrict__ ei,
                              const int* __restrict__ gid) {
    if (blockIdx.x == gridDim.x - 1) {
        int t = threadIdx.x;
        if (t <= NG) {
            int lo = 0, hi = NN;
            while (lo < hi) {
                int mid = (lo + hi) >> 1;
                if (__ldg(&gid[mid]) < t) lo = mid + 1; else hi = mid;
            }
            g_off[t] = lo;
        }
        return;
    }
    int e = blockIdx.x * blockDim.x + threadIdx.x;
    if (e < NE) {
        atomicAdd(&g_deg_out[ei[e]], 1);
        atomicAdd(&g_deg_in[ei[NE + e]], 1);
    }
}

// Bump-allocated CSR segments (order-free) + both norms, one pass.
__global__ void norm_off_kernel() {
    int i = blockIdx.x * blockDim.x + threadIdx.x;
    if (i < NN) {
        int deg = g_deg_in[i];
        int ro = atomicAdd(&g_total, deg);
        g_row_off[i] = ro;
        g_fill[i] = ro;
        g_norm_in[i]  = rsqrtf((float)max(deg, 1));
        g_norm_out[i] = rsqrtf((float)max(g_deg_out[i], 1));
    }
}

__global__ void scatter_kernel(const int* __restrict__ ei) {
    int e = blockIdx.x * blockDim.x + threadIdx.x;
    if (e < NE) {
        int d = ei[NE + e];
        int pos = atomicAdd(&g_fill[d], 1);
        g_csr_src[pos] = ei[e];
    }
}

// ---------------------------------------------------------------------------
// HMMA GEMM: buf1h[n][c] = fp16((X[n] @ W)[c])  — no norm scale (applied in SpMM).
// fp32 -> fp16 hi/lo split: D = Ah*Bh + Ah*Bl + Al*Bh (fp32 accumulators).
#define APAD 72
template <int K, bool FROM_BUF2>
__global__ void __launch_bounds__(256)
gemm_mma_kernel(const float* __restrict__ Xext, const float* __restrict__ W) {
    extern __shared__ __half sm[];
    __half* Ah = sm;
    __half* Al = Ah + 128 * APAD;
    __half* Bh = Al + 128 * APAD;
    __half* Bl = Bh + 64 * APAD;
    const float* X = FROM_BUF2 ? (const float*)g_buf2 : Xext;

    int tid = threadIdx.x;
    int warp = tid >> 5, lane = tid & 31;
    int wm = warp & 3, wn = warp >> 2;
    int n0 = blockIdx.x * 128;

    float d[2][4][4];
#pragma unroll
    for (int mt = 0; mt < 2; ++mt)
#pragma unroll
        for (int nt = 0; nt < 4; ++nt)
#pragma unroll
            for (int q = 0; q < 4; ++q) d[mt][nt][q] = 0.f;

#pragma unroll
    for (int kc = 0; kc < K / 64; ++kc) {
        for (int i = tid; i < 128 * 16; i += 256) {
            int r = i >> 4, jv = i & 15;
            int n = n0 + r;
            float4 v = (n < NN)
                ? __ldg((const float4*)(X + (size_t)n * K + kc * 64) + jv)
                : make_float4(0.f, 0.f, 0.f, 0.f);
            float vv[4] = {v.x, v.y, v.z, v.w};
#pragma unroll
            for (int e = 0; e < 4; ++e) {
                __half h = __float2half_rn(vv[e]);
                __half l = __float2half_rn(vv[e] - __half2float(h));
                Ah[r * APAD + jv * 4 + e] = h;
                Al[r * APAD + jv * 4 + e] = l;
            }
        }
        for (int i = tid; i < 64 * 64; i += 256) {
            int k = i >> 6, n = i & 63;
            float w = __ldg(&W[(kc * 64 + k) * 64 + n]);
            __half h = __float2half_rn(w);
            __half l = __float2half_rn(w - __half2float(h));
            Bh[n * APAD + k] = h;
            Bl[n * APAD + k] = l;
        }
        __syncthreads();

#pragma unroll
        for (int ks = 0; ks < 4; ++ks) {
            uint32_t ah[2][4], al[2][4], bh[4][2], bl[4][2];
#pragma unroll
            for (int mt = 0; mt < 2; ++mt) {
                int row = wm * 32 + mt * 16 + (lane & 15);
                int col = ks * 16 + (lane >> 4) * 8;
                ldm_x4(ah[mt], smem_u32(&Ah[row * APAD + col]));
                ldm_x4(al[mt], smem_u32(&Al[row * APAD + col]));
            }
            int k0 = ks * 16 + (lane & 3) * 2;
#pragma unroll
            for (int nt = 0; nt < 4; ++nt) {
                int n = wn * 32 + nt * 8 + (lane >> 2);
                bh[nt][0] = *(const uint32_t*)&Bh[n * APAD + k0];
                bh[nt][1] = *(const uint32_t*)&Bh[n * APAD + k0 + 8];
                bl[nt][0] = *(const uint32_t*)&Bl[n * APAD + k0];
                bl[nt][1] = *(const uint32_t*)&Bl[n * APAD + k0 + 8];
            }
#pragma unroll
            for (int mt = 0; mt < 2; ++mt)
#pragma unroll
                for (int nt = 0; nt < 4; ++nt) {
                    mma_16816(d[mt][nt], ah[mt], bh[nt]);
                    mma_16816(d[mt][nt], ah[mt], bl[nt]);
                    mma_16816(d[mt][nt], al[mt], bh[nt]);
                }
        }
        __syncthreads();
    }

    // Epilogue: convert to fp16, write buf1h (half2 stores)
#pragma unroll
    for (int mt = 0; mt < 2; ++mt) {
        int r0 = n0 + wm * 32 + mt * 16 + (lane >> 2);
        int r1 = r0 + 8;
#pragma unroll
        for (int nt = 0; nt < 4; ++nt) {
            int c = wn * 32 + nt * 8 + (lane & 3) * 2;
            if (r0 < NN) {
                __half2 o = __floats2half2_rn(d[mt][nt][0], d[mt][nt][1]);
                *(__half2*)&g_buf1h[(size_t)r0 * 64 + c] = o;
            }
            if (r1 < NN) {
                __half2 o = __floats2half2_rn(d[mt][nt][2], d[mt][nt][3]);
                *(__half2*)&g_buf1h[(size_t)r1 * 64 + c] = o;
            }
        }
    }
}
#define GEMM_SMEM ((2 * 128 * APAD + 2 * 64 * APAD) * 2)

// ---------------------------------------------------------------------------
// CSR SpMM + fused epilogue. One warp per dst node, half2 per lane (128B rows),
// per-edge norm_out scale (broadcast load), fp32 accumulation, 8-way ILP.
template <bool FINAL>
__global__ void spmm_kernel(const float* __restrict__ bias,
                            const float* __restrict__ aW,
                            const float* __restrict__ ab,
                            float* __restrict__ hw_out) {
    int n = blockIdx.x * 8 + (threadIdx.x >> 5);
    if (n >= NN) return;
    int lane = threadIdx.x & 31;
    int beg = g_row_off[n];
    int end = beg + g_deg_in[n];
    const __half2* B1 = (const __half2*)g_buf1h;   // row stride 32 half2
    float2 acc = make_float2(0.f, 0.f);
    int k = beg;
    for (; k + 8 <= end; k += 8) {
        int s[8]; float no[8]; float2 v[8];
#pragma unroll
        for (int q = 0; q < 8; ++q) s[q] = __ldg(&g_csr_src[k + q]);
#pragma unroll
        for (int q = 0; q < 8; ++q) no[q] = __ldg(&g_norm_out[s[q]]);
#pragma unroll
        for (int q = 0; q < 8; ++q)
            v[q] = __half22float2(B1[(size_t)s[q] * 32 + lane]);
#pragma unroll
        for (int q = 0; q < 8; ++q) {
            acc.x += v[q].x * no[q];
            acc.y += v[q].y * no[q];
        }
    }
    for (; k < end; ++k) {
        int s = __ldg(&g_csr_src[k]);
        float no = __ldg(&g_norm_out[s]);
        float2 v = __half22float2(B1[(size_t)s * 32 + lane]);
        acc.x += v.x * no; acc.y += v.y * no;
    }
    float ni = g_norm_in[n];
    float2 b = ((const float2*)bias)[lane];
    float2 h;
    h.x = fmaxf(acc.x * ni + b.x, 0.f);
    h.y = fmaxf(acc.y * ni + b.y, 0.f);
    float2* B2 = (float2*)g_buf2;
    if (!FINAL) {
        B2[(size_t)n * 32 + lane] = h;
    } else {
        float2 a = ((const float2*)aW)[lane];
        float p = h.x * a.x + h.y * a.y;
#pragma unroll
        for (int o = 16; o; o >>= 1) p += __shfl_xor_sync(0xffffffffu, p, o);
        float hw = 1.f / (1.f + __expf(-(p + __ldg(&ab[0]))));
        if (lane == 0) hw_out[n] = hw;
        B2[(size_t)n * 32 + lane] = make_float2(h.x * hw, h.y * hw);
    }
}

// ---------------------------------------------------------------------------
__global__ void pool_cls_kernel(const float* __restrict__ clsW,
                                const float* __restrict__ clsb,
                                float* __restrict__ out) {
    __shared__ float part[8][64];
    __shared__ float meanv[64];
    int g = blockIdx.x;
    int tid = threadIdx.x;
    int c = tid & 63, s = tid >> 6;
    int start = g_off[g], end = g_off[g + 1];
    float acc = 0.f;
    for (int n = start + s; n < end; n += 8)
        acc += ((const float*)g_buf2)[(size_t)n * 64 + c];
    part[s][c] = acc;
    __syncthreads();
    if (s == 0) {
        float tot = 0.f;
#pragma unroll
        for (int q = 0; q < 8; q++) tot += part[q][c];
        float cnt = fmaxf((float)(end - start), 1.f);
        meanv[c] = tot / cnt;
    }
    __syncthreads();
    if (tid < 10) {
        float a2 = __ldg(&clsb[tid]);
#pragma unroll
        for (int kk = 0; kk < 64; kk++)
            a2 += meanv[kk] * __ldg(&clsW[kk * 10 + tid]);
        out[g * 10 + tid] = a2;
    }
}

// ---------------------------------------------------------------------------
extern "C" void kernel_launch(void* const* d_in, const int* in_sizes, int n_in,
                              void* d_out, int out_size) {
    const float* x   = (const float*)d_in[0];
    const int*   ei  = (const int*)  d_in[1];
    const int*   gid = (const int*)  d_in[2];
    const float* W1  = (const float*)d_in[3];
    const float* b1  = (const float*)d_in[4];
    const float* W2  = (const float*)d_in[5];
    const float* b2  = (const float*)d_in[6];
    const float* aW  = (const float*)d_in[7];
    const float* ab  = (const float*)d_in[8];
    const float* cW  = (const float*)d_in[9];
    const float* cb  = (const float*)d_in[10];
    float* out = (float*)d_out;
    float* hw  = out + NG * 10;

    static cudaStream_t s2 = nullptr;
    static cudaEvent_t evF = nullptr, evJ = nullptr;
    if (!s2) {   // first call is the (uncaptured) correctness run
        cudaStreamCreateWithFlags(&s2, cudaStreamNonBlocking);
        cudaEventCreateWithFlags(&evF, cudaEventDisableTiming);
        cudaEventCreateWithFlags(&evJ, cudaEventDisableTiming);
        cudaFuncSetAttribute(gemm_mma_kernel<INDIM, false>,
                             cudaFuncAttributeMaxDynamicSharedMemorySize, GEMM_SMEM);
        cudaFuncSetAttribute(gemm_mma_kernel<HID, true>,
                             cudaFuncAttributeMaxDynamicSharedMemorySize, GEMM_SMEM);
    }

    // Fork: GEMM1 (reads only x, W1) overlaps the CSR build chain.
    cudaEventRecord(evF, 0);
    cudaStreamWaitEvent(s2, evF, 0);
    gemm_mma_kernel<INDIM, false><<<(NN + 127) / 128, 256, GEMM_SMEM, s2>>>(x, W1);
    cudaEventRecord(evJ, s2);

    // CSR build on the main (capture) stream.
    zero_kernel<<<(NN + 255) / 256, 256>>>();
    degree_kernel<<<(NE + 255) / 256 + 1, 256>>>(ei, gid);
    norm_off_kernel<<<(NN + 255) / 256, 256>>>();
    scatter_kernel<<<(NE + 255) / 256, 256>>>(ei);

    // Join, then the dependent chain.
    cudaStreamWaitEvent(0, evJ, 0);
    spmm_kernel<false><<<(NN + 7) / 8, 256>>>(b1, nullptr, nullptr, nullptr);

    gemm_mma_kernel<HID, true><<<(NN + 127) / 128, 256, GEMM_SMEM>>>(nullptr, W2);
    spmm_kernel<true><<<(NN + 7) / 8, 256>>>(b2, aW, ab, hw);

    pool_cls_kernel<<<NG, 512>>>(cW, cb, out);
}

// round 12
// speedup vs baseline: 1.4814x; 1.4814x over previous
#include <cuda_runtime.h>
#include <cuda_bf16.h>
#include <cuda_fp16.h>
#include <cstdint>

#define NN 100000
#define NE 1600000
#define NG 64
#define HID 64
#define INDIM 128

#define GB1 ((NN + 127) / 128)            // 782 gemm1 blocks
#define DEGB ((NE + 2047) / 2048)         // 782 degree blocks (8 edges/thread)
#define SCATB ((NE + 255) / 256)          // 6250 scatter blocks
#define SCALB (NN * 64 / 8 / 256)         // 3125 scale blocks

// Scratch (__device__ globals per alloc-free rule)
__device__ __half g_buf1h[NN * 64];  // SpMM source rows, fp16
__device__ float4 g_buf2[NN * 16];   // activations / gated output (fp32)
__device__ float  g_norm_out[NN];
__device__ float  g_norm_in[NN];
__device__ int    g_deg_out[NN];
__device__ int    g_deg_in[NN];
__device__ int    g_fill[NN];
__device__ int    g_row_off[NN];
__device__ int    g_csr_src[NE];
__device__ int    g_total;
__device__ int    g_off[NG + 1];

// ---------------------------------------------------------------------------
__device__ __forceinline__ uint32_t smem_u32(const void* p) {
    uint32_t a;
    asm("{ .reg .u64 t; cvta.to.shared.u64 t, %1; cvt.u32.u64 %0, t; }"
        : "=r"(a) : "l"(p));
    return a;
}
__device__ __forceinline__ void ldm_x4(uint32_t* r, uint32_t addr) {
    asm volatile("ldmatrix.sync.aligned.m8n8.x4.shared.b16 {%0,%1,%2,%3}, [%4];"
                 : "=r"(r[0]), "=r"(r[1]), "=r"(r[2]), "=r"(r[3]) : "r"(addr));
}
__device__ __forceinline__ void mma_16816(float* d, const uint32_t* a,
                                          const uint32_t* b) {
    asm volatile("mma.sync.aligned.m16n8k16.row.col.f32.f16.f16.f32 "
                 "{%0,%1,%2,%3}, {%4,%5,%6,%7}, {%8,%9}, {%0,%1,%2,%3};"
                 : "+f"(d[0]), "+f"(d[1]), "+f"(d[2]), "+f"(d[3])
                 : "r"(a[0]), "r"(a[1]), "r"(a[2]), "r"(a[3]),
                   "r"(b[0]), "r"(b[1]));
}

// ---------------------------------------------------------------------------
__global__ void zero_kernel() {
    int i = blockIdx.x * blockDim.x + threadIdx.x;
    if (i < NN) { g_deg_out[i] = 0; g_deg_in[i] = 0; }
    if (i == 0) g_total = 0;
}

// ---------------------------------------------------------------------------
// FAT 1: blocks [0,GB1) = GEMM1 (K=128, chunk 32, ~30.7KB smem, unscaled fp16
// output); blocks [GB1, GB1+DEGB) = degrees (8 edges/thread, RED); last block
// = graph segment bounds. GEMM blocks first -> scheduled first.
#define APAD2 40
__global__ void __launch_bounds__(256)
fat1_kernel(const int* __restrict__ ei, const int* __restrict__ gid,
            const float* __restrict__ X, const float* __restrict__ W) {
    if (blockIdx.x < GB1) {
        extern __shared__ __half sm[];
        __half* Ah = sm;                       // 128 x 40
        __half* Al = Ah + 128 * APAD2;
        __half* Bh = Al + 128 * APAD2;         // 64 x 40
        __half* Bl = Bh + 64 * APAD2;
        int tid = threadIdx.x;
        int warp = tid >> 5, lane = tid & 31;
        int wm = warp & 3, wn = warp >> 2;
        int n0 = blockIdx.x * 128;

        float d[2][4][4];
#pragma unroll
        for (int mt = 0; mt < 2; ++mt)
#pragma unroll
            for (int nt = 0; nt < 4; ++nt)
#pragma unroll
                for (int q = 0; q < 4; ++q) d[mt][nt][q] = 0.f;

#pragma unroll
        for (int kc = 0; kc < 4; ++kc) {
            for (int i = tid; i < 128 * 8; i += 256) {
                int r = i >> 3, jv = i & 7;
                int n = n0 + r;
                float4 v = (n < NN)
                    ? __ldg((const float4*)(X + (size_t)n * INDIM + kc * 32) + jv)
                    : make_float4(0.f, 0.f, 0.f, 0.f);
                float vv[4] = {v.x, v.y, v.z, v.w};
#pragma unroll
                for (int e = 0; e < 4; ++e) {
                    __half h = __float2half_rn(vv[e]);
                    __half l = __float2half_rn(vv[e] - __half2float(h));
                    Ah[r * APAD2 + jv * 4 + e] = h;
                    Al[r * APAD2 + jv * 4 + e] = l;
                }
            }
            for (int i = tid; i < 64 * 32; i += 256) {
                int k = i >> 6, n = i & 63;
                float w = __ldg(&W[(kc * 32 + k) * 64 + n]);
                __half h = __float2half_rn(w);
                __half l = __float2half_rn(w - __half2float(h));
                Bh[n * APAD2 + k] = h;
                Bl[n * APAD2 + k] = l;
            }
            __syncthreads();
#pragma unroll
            for (int ks = 0; ks < 2; ++ks) {
                uint32_t ah[2][4], al[2][4], bh[4][2], bl[4][2];
#pragma unroll
                for (int mt = 0; mt < 2; ++mt) {
                    int row = wm * 32 + mt * 16 + (lane & 15);
                    int col = ks * 16 + (lane >> 4) * 8;
                    ldm_x4(ah[mt], smem_u32(&Ah[row * APAD2 + col]));
                    ldm_x4(al[mt], smem_u32(&Al[row * APAD2 + col]));
                }
                int k0 = ks * 16 + (lane & 3) * 2;
#pragma unroll
                for (int nt = 0; nt < 4; ++nt) {
                    int nn = wn * 32 + nt * 8 + (lane >> 2);
                    bh[nt][0] = *(const uint32_t*)&Bh[nn * APAD2 + k0];
                    bh[nt][1] = *(const uint32_t*)&Bh[nn * APAD2 + k0 + 8];
                    bl[nt][0] = *(const uint32_t*)&Bl[nn * APAD2 + k0];
                    bl[nt][1] = *(const uint32_t*)&Bl[nn * APAD2 + k0 + 8];
                }
#pragma unroll
                for (int mt = 0; mt < 2; ++mt)
#pragma unroll
                    for (int nt = 0; nt < 4; ++nt) {
                        mma_16816(d[mt][nt], ah[mt], bh[nt]);
                        mma_16816(d[mt][nt], ah[mt], bl[nt]);
                        mma_16816(d[mt][nt], al[mt], bh[nt]);
                    }
            }
            __syncthreads();
        }
        // unscaled fp16 epilogue (norm applied later in fat2 scale pass)
#pragma unroll
        for (int mt = 0; mt < 2; ++mt) {
            int r0 = n0 + wm * 32 + mt * 16 + (lane >> 2);
            int r1 = r0 + 8;
#pragma unroll
            for (int nt = 0; nt < 4; ++nt) {
                int c = wn * 32 + nt * 8 + (lane & 3) * 2;
                if (r0 < NN) {
                    __half2 o = __floats2half2_rn(d[mt][nt][0], d[mt][nt][1]);
                    *(__half2*)&g_buf1h[(size_t)r0 * 64 + c] = o;
                }
                if (r1 < NN) {
                    __half2 o = __floats2half2_rn(d[mt][nt][2], d[mt][nt][3]);
                    *(__half2*)&g_buf1h[(size_t)r1 * 64 + c] = o;
                }
            }
        }
        return;
    }

    int b = blockIdx.x - GB1;
    if (b < DEGB) {
        int base = b * 2048 + threadIdx.x * 8;
        if (base + 8 <= NE) {
            int4 s0 = *(const int4*)&ei[base];
            int4 s1 = *(const int4*)&ei[base + 4];
            int4 d0 = *(const int4*)&ei[NE + base];
            int4 d1 = *(const int4*)&ei[NE + base + 4];
            atomicAdd(&g_deg_out[s0.x], 1); atomicAdd(&g_deg_out[s0.y], 1);
            atomicAdd(&g_deg_out[s0.z], 1); atomicAdd(&g_deg_out[s0.w], 1);
            atomicAdd(&g_deg_out[s1.x], 1); atomicAdd(&g_deg_out[s1.y], 1);
            atomicAdd(&g_deg_out[s1.z], 1); atomicAdd(&g_deg_out[s1.w], 1);
            atomicAdd(&g_deg_in[d0.x], 1);  atomicAdd(&g_deg_in[d0.y], 1);
            atomicAdd(&g_deg_in[d0.z], 1);  atomicAdd(&g_deg_in[d0.w], 1);
            atomicAdd(&g_deg_in[d1.x], 1);  atomicAdd(&g_deg_in[d1.y], 1);
            atomicAdd(&g_deg_in[d1.z], 1);  atomicAdd(&g_deg_in[d1.w], 1);
        } else {
            for (int q = 0; q < 8; ++q) {
                int e = base + q;
                if (e < NE) {
                    atomicAdd(&g_deg_out[ei[e]], 1);
                    atomicAdd(&g_deg_in[ei[NE + e]], 1);
                }
            }
        }
        return;
    }

    // last block: graph segment bounds via binary search on sorted gid
    int t = threadIdx.x;
    if (t <= NG) {
        int lo = 0, hi = NN;
        while (lo < hi) {
            int mid = (lo + hi) >> 1;
            if (__ldg(&gid[mid]) < t) lo = mid + 1; else hi = mid;
        }
        g_off[t] = lo;
    }
}
#define FAT1_SMEM ((2 * 128 * APAD2 + 2 * 64 * APAD2) * 2)

// Bump-allocated CSR segments (order-free) + both norms, one pass.
__global__ void norm_off_kernel() {
    int i = blockIdx.x * blockDim.x + threadIdx.x;
    if (i < NN) {
        int deg = g_deg_in[i];
        int ro = atomicAdd(&g_total, deg);
        g_row_off[i] = ro;
        g_fill[i] = ro;
        g_norm_in[i]  = rsqrtf((float)max(deg, 1));
        g_norm_out[i] = rsqrtf((float)max(g_deg_out[i], 1));
    }
}

// FAT 2: blocks [0,SCATB) = CSR scatter; rest = scale buf1h rows by norm_out
// (the GEMM1 norm scaling deferred from fat1; hidden behind the atomic scatter).
__global__ void fat2_kernel(const int* __restrict__ ei) {
    if (blockIdx.x < SCATB) {
        int e = blockIdx.x * 256 + threadIdx.x;
        if (e < NE) {
            int d = ei[NE + e];
            int pos = atomicAdd(&g_fill[d], 1);
            g_csr_src[pos] = ei[e];
        }
        return;
    }
    int idx = (blockIdx.x - SCATB) * 256 + threadIdx.x;  // [0, NN*8)
    int n = idx >> 3, ch = idx & 7;
    float no = g_norm_out[n];
    __half2* p = (__half2*)&g_buf1h[(size_t)n * 64 + ch * 8];
#pragma unroll
    for (int q = 0; q < 4; ++q) {
        float2 v = __half22float2(p[q]);
        p[q] = __floats2half2_rn(v.x * no, v.y * no);
    }
}

// ---------------------------------------------------------------------------
// HMMA GEMM2 (K=64): buf1h[n][c] = fp16((buf2[n] @ W)[c] * norm_out[n]).
#define APAD 72
__global__ void __launch_bounds__(256)
gemm2_kernel(const float* __restrict__ W) {
    extern __shared__ __half sm[];
    __half* Ah = sm;
    __half* Al = Ah + 128 * APAD;
    __half* Bh = Al + 128 * APAD;
    __half* Bl = Bh + 64 * APAD;
    const float* X = (const float*)g_buf2;

    int tid = threadIdx.x;
    int warp = tid >> 5, lane = tid & 31;
    int wm = warp & 3, wn = warp >> 2;
    int n0 = blockIdx.x * 128;

    float d[2][4][4];
#pragma unroll
    for (int mt = 0; mt < 2; ++mt)
#pragma unroll
        for (int nt = 0; nt < 4; ++nt)
#pragma unroll
            for (int q = 0; q < 4; ++q) d[mt][nt][q] = 0.f;

    for (int i = tid; i < 128 * 16; i += 256) {
        int r = i >> 4, jv = i & 15;
        int n = n0 + r;
        float4 v = (n < NN)
            ? __ldg((const float4*)(X + (size_t)n * HID) + jv)
            : make_float4(0.f, 0.f, 0.f, 0.f);
        float vv[4] = {v.x, v.y, v.z, v.w};
#pragma unroll
        for (int e = 0; e < 4; ++e) {
            __half h = __float2half_rn(vv[e]);
            __half l = __float2half_rn(vv[e] - __half2float(h));
            Ah[r * APAD + jv * 4 + e] = h;
            Al[r * APAD + jv * 4 + e] = l;
        }
    }
    for (int i = tid; i < 64 * 64; i += 256) {
        int k = i >> 6, n = i & 63;
        float w = __ldg(&W[k * 64 + n]);
        __half h = __float2half_rn(w);
        __half l = __float2half_rn(w - __half2float(h));
        Bh[n * APAD + k] = h;
        Bl[n * APAD + k] = l;
    }
    __syncthreads();

#pragma unroll
    for (int ks = 0; ks < 4; ++ks) {
        uint32_t ah[2][4], al[2][4], bh[4][2], bl[4][2];
#pragma unroll
        for (int mt = 0; mt < 2; ++mt) {
            int row = wm * 32 + mt * 16 + (lane & 15);
            int col = ks * 16 + (lane >> 4) * 8;
            ldm_x4(ah[mt], smem_u32(&Ah[row * APAD + col]));
            ldm_x4(al[mt], smem_u32(&Al[row * APAD + col]));
        }
        int k0 = ks * 16 + (lane & 3) * 2;
#pragma unroll
        for (int nt = 0; nt < 4; ++nt) {
            int n = wn * 32 + nt * 8 + (lane >> 2);
            bh[nt][0] = *(const uint32_t*)&Bh[n * APAD + k0];
            bh[nt][1] = *(const uint32_t*)&Bh[n * APAD + k0 + 8];
            bl[nt][0] = *(const uint32_t*)&Bl[n * APAD + k0];
            bl[nt][1] = *(const uint32_t*)&Bl[n * APAD + k0 + 8];
        }
#pragma unroll
        for (int mt = 0; mt < 2; ++mt)
#pragma unroll
            for (int nt = 0; nt < 4; ++nt) {
                mma_16816(d[mt][nt], ah[mt], bh[nt]);
                mma_16816(d[mt][nt], ah[mt], bl[nt]);
                mma_16816(d[mt][nt], al[mt], bh[nt]);
            }
    }

#pragma unroll
    for (int mt = 0; mt < 2; ++mt) {
        int r0 = n0 + wm * 32 + mt * 16 + (lane >> 2);
        int r1 = r0 + 8;
        float s0 = (r0 < NN) ? g_norm_out[r0] : 0.f;
        float s1 = (r1 < NN) ? g_norm_out[r1] : 0.f;
#pragma unroll
        for (int nt = 0; nt < 4; ++nt) {
            int c = wn * 32 + nt * 8 + (lane & 3) * 2;
            if (r0 < NN) {
                __half2 o = __floats2half2_rn(d[mt][nt][0] * s0, d[mt][nt][1] * s0);
                *(__half2*)&g_buf1h[(size_t)r0 * 64 + c] = o;
            }
            if (r1 < NN) {
                __half2 o = __floats2half2_rn(d[mt][nt][2] * s1, d[mt][nt][3] * s1);
                *(__half2*)&g_buf1h[(size_t)r1 * 64 + c] = o;
            }
        }
    }
}
#define GEMM_SMEM ((2 * 128 * APAD + 2 * 64 * APAD) * 2)

// ---------------------------------------------------------------------------
// CSR SpMM + fused epilogue. One warp per dst node, half2 per lane (128B rows),
// fp32 accumulation, 8-way ILP.
template <bool FINAL>
__global__ void spmm_kernel(const float* __restrict__ bias,
                            const float* __restrict__ aW,
                            const float* __restrict__ ab,
                            float* __restrict__ hw_out) {
    int n = blockIdx.x * 8 + (threadIdx.x >> 5);
    if (n >= NN) return;
    int lane = threadIdx.x & 31;
    int beg = g_row_off[n];
    int end = beg + g_deg_in[n];
    const __half2* B1 = (const __half2*)g_buf1h;   // row stride 32 half2
    float2 acc = make_float2(0.f, 0.f);
    int k = beg;
    for (; k + 8 <= end; k += 8) {
        int s[8]; float2 v[8];
#pragma unroll
        for (int q = 0; q < 8; ++q) s[q] = __ldg(&g_csr_src[k + q]);
#pragma unroll
        for (int q = 0; q < 8; ++q)
            v[q] = __half22float2(B1[(size_t)s[q] * 32 + lane]);
#pragma unroll
        for (int q = 0; q < 8; ++q) {
            acc.x += v[q].x;
            acc.y += v[q].y;
        }
    }
    for (; k < end; ++k) {
        int s = __ldg(&g_csr_src[k]);
        float2 v = __half22float2(B1[(size_t)s * 32 + lane]);
        acc.x += v.x; acc.y += v.y;
    }
    float ni = g_norm_in[n];
    float2 b = ((const float2*)bias)[lane];
    float2 h;
    h.x = fmaxf(acc.x * ni + b.x, 0.f);
    h.y = fmaxf(acc.y * ni + b.y, 0.f);
    float2* B2 = (float2*)g_buf2;
    if (!FINAL) {
        B2[(size_t)n * 32 + lane] = h;
    } else {
        float2 a = ((const float2*)aW)[lane];
        float p = h.x * a.x + h.y * a.y;
#pragma unroll
        for (int o = 16; o; o >>= 1) p += __shfl_xor_sync(0xffffffffu, p, o);
        float hw = 1.f / (1.f + __expf(-(p + __ldg(&ab[0]))));
        if (lane == 0) hw_out[n] = hw;
        B2[(size_t)n * 32 + lane] = make_float2(h.x * hw, h.y * hw);
    }
}

// ---------------------------------------------------------------------------
__global__ void pool_cls_kernel(const float* __restrict__ clsW,
                                const float* __restrict__ clsb,
                                float* __restrict__ out) {
    __shared__ float part[8][64];
    __shared__ float meanv[64];
    int g = blockIdx.x;
    int tid = threadIdx.x;
    int c = tid & 63, s = tid >> 6;
    int start = g_off[g], end = g_off[g + 1];
    float acc = 0.f;
    for (int n = start + s; n < end; n += 8)
        acc += ((const float*)g_buf2)[(size_t)n * 64 + c];
    part[s][c] = acc;
    __syncthreads();
    if (s == 0) {
        float tot = 0.f;
#pragma unroll
        for (int q = 0; q < 8; q++) tot += part[q][c];
        float cnt = fmaxf((float)(end - start), 1.f);
        meanv[c] = tot / cnt;
    }
    __syncthreads();
    if (tid < 10) {
        float a2 = __ldg(&clsb[tid]);
#pragma unroll
        for (int kk = 0; kk < 64; kk++)
            a2 += meanv[kk] * __ldg(&clsW[kk * 10 + tid]);
        out[g * 10 + tid] = a2;
    }
}

// ---------------------------------------------------------------------------
extern "C" void kernel_launch(void* const* d_in, const int* in_sizes, int n_in,
                              void* d_out, int out_size) {
    const float* x   = (const float*)d_in[0];
    const int*   ei  = (const int*)  d_in[1];
    const int*   gid = (const int*)  d_in[2];
    const float* W1  = (const float*)d_in[3];
    const float* b1  = (const float*)d_in[4];
    const float* W2  = (const float*)d_in[5];
    const float* b2  = (const float*)d_in[6];
    const float* aW  = (const float*)d_in[7];
    const float* ab  = (const float*)d_in[8];
    const float* cW  = (const float*)d_in[9];
    const float* cb  = (const float*)d_in[10];
    float* out = (float*)d_out;
    float* hw  = out + NG * 10;

    static bool attr_done = false;
    if (!attr_done) {
        cudaFuncSetAttribute(fat1_kernel,
                             cudaFuncAttributeMaxDynamicSharedMemorySize, FAT1_SMEM);
        cudaFuncSetAttribute(gemm2_kernel,
                             cudaFuncAttributeMaxDynamicSharedMemorySize, GEMM_SMEM);
        attr_done = true;
    }

    zero_kernel<<<(NN + 255) / 256, 256>>>();
    // GEMM1 + degrees + graph bounds, one launch (overlap without streams)
    fat1_kernel<<<GB1 + DEGB + 1, 256, FAT1_SMEM>>>(ei, gid, x, W1);
    norm_off_kernel<<<(NN + 255) / 256, 256>>>();
    // scatter + deferred norm_out scaling of buf1h, one launch
    fat2_kernel<<<SCATB + SCALB, 256>>>(ei);

    spmm_kernel<false><<<(NN + 7) / 8, 256>>>(b1, nullptr, nullptr, nullptr);
    gemm2_kernel<<<(NN + 127) / 128, 256, GEMM_SMEM>>>(W2);
    spmm_kernel<true><<<(NN + 7) / 8, 256>>>(b2, aW, ab, hw);
    pool_cls_kernel<<<NG, 512>>>(cW, cb, out);
}